// round 1
// baseline (speedup 1.0000x reference)
#include <cuda_runtime.h>
#include <math.h>

#define VV   2048
#define EE   512
#define HH   1024
#define BB   128
#define LL   256
#define H3   3072
#define LDEC 255
#define MENC (LL*BB)      /* 32768 */
#define MDEC (LDEC*BB)    /* 32640 */
#define EH   (EE+HH)      /* 1536 */
#define E2H  (EE+2*HH)    /* 2560 */
#define RGRID 128

// ---------------- scratch (static device allocations only) ----------------
static __device__ int   g_idx_enc[MENC];
static __device__ int   g_idx_dec[MDEC];
static __device__ float g_gi_enc[(size_t)MENC*H3];   // (L, B, 3H) encoder input gates
static __device__ float g_gi_dec[(size_t)MDEC*H3];   // (L-1, B, 3H) decoder e_t gates
static __device__ float g_gic[BB*H3];                // context part of decoder input gates
static __device__ float g_hA[BB*HH];
static __device__ float g_hB[BB*HH];
static __device__ float g_ctx[BB*HH];
static __device__ float g_h2[(size_t)MDEC*HH];       // all decoder hidden states
static __device__ float g_P[(size_t)MDEC*VV];        // accumulated fc output (time-major)
static __device__ float g_Pc[BB*VV];                 // context part of fc output
static __device__ unsigned g_arrive;

// ---------------- tiny helpers ----------------
__global__ void k_build_idx(const int* __restrict__ seq) {
    int i = blockIdx.x * blockDim.x + threadIdx.x;
    if (i < MENC) { int t = i / BB, b = i % BB; g_idx_enc[i] = seq[b*LL + t]; }
    if (i < MDEC) { int t = i / BB, b = i % BB; g_idx_dec[i] = seq[b*LL + t]; }
}

__global__ void k_reset_bar() { g_arrive = 0u; }

__global__ void k_copy(float* __restrict__ dst, const float* __restrict__ src, int n) {
    int i = blockIdx.x * blockDim.x + threadIdx.x;
    if (i < n) dst[i] = src[i];
}

// ---------------- generic fp32 NT GEMM: C[M,N] (+)= gather(A)[M,K] @ Bw[N,K]^T + bias ----
// BM=128, BN=64, BK=16, 256 threads, 8x4 per-thread microtile.
__global__ __launch_bounds__(256) void k_gemm(
    const float* __restrict__ A, int lda, const int* __restrict__ idx,
    const float* __restrict__ Bw, int ldb, int bofs,
    const float* __restrict__ bias,
    float* __restrict__ C, int N, int K, int accumulate)
{
    __shared__ float As[16][132];
    __shared__ float Bs[16][68];
    const int m0 = blockIdx.y * 128;
    const int n0 = blockIdx.x * 64;
    const int tid = threadIdx.x;
    const int rg = tid >> 4;   // 0..15
    const int cg = tid & 15;   // 0..15

    float acc[8][4];
#pragma unroll
    for (int i = 0; i < 8; i++)
#pragma unroll
        for (int j = 0; j < 4; j++) acc[i][j] = 0.f;

    const int r0  = tid >> 2;          // 0..63
    const int r1  = r0 + 64;
    const int kq0 = (tid & 3) * 4;
    const int ga0 = m0 + r0;
    const int ga1 = m0 + r1;
    const size_t aoff0 = (size_t)(idx ? idx[ga0] : ga0) * lda;
    const size_t aoff1 = (size_t)(idx ? idx[ga1] : ga1) * lda;
    const size_t boff  = (size_t)(n0 + r0) * ldb + bofs;

    for (int k0 = 0; k0 < K; k0 += 16) {
        float4 va0 = *reinterpret_cast<const float4*>(A + aoff0 + k0 + kq0);
        float4 va1 = *reinterpret_cast<const float4*>(A + aoff1 + k0 + kq0);
        float4 vb  = *reinterpret_cast<const float4*>(Bw + boff + k0 + kq0);
        As[kq0+0][r0] = va0.x; As[kq0+1][r0] = va0.y; As[kq0+2][r0] = va0.z; As[kq0+3][r0] = va0.w;
        As[kq0+0][r1] = va1.x; As[kq0+1][r1] = va1.y; As[kq0+2][r1] = va1.z; As[kq0+3][r1] = va1.w;
        Bs[kq0+0][r0] = vb.x;  Bs[kq0+1][r0] = vb.y;  Bs[kq0+2][r0] = vb.z;  Bs[kq0+3][r0] = vb.w;
        __syncthreads();
#pragma unroll
        for (int kk = 0; kk < 16; kk++) {
            float4 a0 = *reinterpret_cast<const float4*>(&As[kk][rg*8]);
            float4 a1 = *reinterpret_cast<const float4*>(&As[kk][rg*8+4]);
            float4 b  = *reinterpret_cast<const float4*>(&Bs[kk][cg*4]);
            float av[8] = {a0.x,a0.y,a0.z,a0.w,a1.x,a1.y,a1.z,a1.w};
            float bv[4] = {b.x,b.y,b.z,b.w};
#pragma unroll
            for (int i = 0; i < 8; i++)
#pragma unroll
                for (int j = 0; j < 4; j++) acc[i][j] += av[i]*bv[j];
        }
        __syncthreads();
    }

    float4 bb = make_float4(0.f,0.f,0.f,0.f);
    if (bias) bb = *reinterpret_cast<const float4*>(bias + n0 + cg*4);
#pragma unroll
    for (int i = 0; i < 8; i++) {
        float* cp = C + (size_t)(m0 + rg*8 + i) * N + n0 + cg*4;
        float4 v = make_float4(acc[i][0]+bb.x, acc[i][1]+bb.y, acc[i][2]+bb.z, acc[i][3]+bb.w);
        if (accumulate) {
            float4 p = *reinterpret_cast<const float4*>(cp);
            v.x += p.x; v.y += p.y; v.z += p.z; v.w += p.w;
        }
        *reinterpret_cast<float4*>(cp) = v;
    }
}

// ---------------- grid barrier (manual, persistent-kernel) ----------------
__device__ __forceinline__ void grid_bar(unsigned want) {
    __threadfence();
    __syncthreads();
    if (threadIdx.x == 0) {
        atomicAdd(&g_arrive, 1u);
        volatile unsigned* p = &g_arrive;
        while (*p < want) { }
    }
    __syncthreads();
}

// ---------------- persistent recurrent kernel (GRU over T steps) ----------------
// Block bid owns h-columns j0..j0+7 across all 3 gates (24 output cols, K=HH).
// One grid barrier per step; h ping-pongs between h0buf/h1buf; cross-SM traffic via .cg.
__global__ __launch_bounds__(256) void k_rec(
    const float* __restrict__ Whh,      // [3H, H]
    const float* __restrict__ bhh,      // [3H]
    const float* __restrict__ gi,       // [T, B, 3H] (includes b_ih)
    const float* __restrict__ giextra,  // [B, 3H] or null (decoder context term)
    float* __restrict__ h0buf, float* __restrict__ h1buf,
    float* __restrict__ h2store,        // [T, B, H] or null
    int T, int initzero)
{
    __shared__ float hs[16][132];
    __shared__ float Ws[16][28];
    const int tid = threadIdx.x;
    const int bid = blockIdx.x;
    const int j0  = bid * 8;
    const int rg  = tid >> 3;   // 0..31 -> rows rg*4..rg*4+3
    const int jj  = tid & 7;
    const int j   = j0 + jj;

    unsigned barno = 0;
    if (initzero) {
        for (int i = bid*256 + tid; i < BB*HH; i += RGRID*256) h0buf[i] = 0.f;
    }
    barno++; grid_bar(barno * RGRID);

    // W staging indices (only tid < 96 loads: 24 rows x 16 k = 96 float4)
    const int wc  = tid >> 2;           // 0..63 (only <24 valid)
    const int wkq = (tid & 3) * 4;
    size_t woff = 0;
    if (tid < 96) {
        int g = wc >> 3, j2 = wc & 7;
        woff = (size_t)(g*HH + j0 + j2) * HH + wkq;
    }
    const int hrow = tid >> 2;          // 0..63
    const int hkq  = (tid & 3) * 4;

    const float bh0 = bhh[j], bh1 = bhh[HH + j], bh2 = bhh[2*HH + j];

    for (int t = 0; t < T; t++) {
        const float* __restrict__ h  = (t & 1) ? h1buf : h0buf;
        float*       __restrict__ hn = (t & 1) ? h0buf : h1buf;
        float acc[4][3];
#pragma unroll
        for (int r = 0; r < 4; r++) { acc[r][0] = 0.f; acc[r][1] = 0.f; acc[r][2] = 0.f; }

        for (int k0 = 0; k0 < HH; k0 += 16) {
            float4 v0 = __ldcg(reinterpret_cast<const float4*>(h + (size_t)hrow*HH + k0 + hkq));
            float4 v1 = __ldcg(reinterpret_cast<const float4*>(h + (size_t)(hrow+64)*HH + k0 + hkq));
            float4 vw = make_float4(0.f,0.f,0.f,0.f);
            if (tid < 96) vw = *reinterpret_cast<const float4*>(Whh + woff + k0);
            hs[hkq+0][hrow]    = v0.x; hs[hkq+1][hrow]    = v0.y; hs[hkq+2][hrow]    = v0.z; hs[hkq+3][hrow]    = v0.w;
            hs[hkq+0][hrow+64] = v1.x; hs[hkq+1][hrow+64] = v1.y; hs[hkq+2][hrow+64] = v1.z; hs[hkq+3][hrow+64] = v1.w;
            if (tid < 96) { Ws[wkq+0][wc] = vw.x; Ws[wkq+1][wc] = vw.y; Ws[wkq+2][wc] = vw.z; Ws[wkq+3][wc] = vw.w; }
            __syncthreads();
#pragma unroll
            for (int kk = 0; kk < 16; kk++) {
                float4 hv = *reinterpret_cast<const float4*>(&hs[kk][rg*4]);
                float w0 = Ws[kk][jj], w1 = Ws[kk][8+jj], w2 = Ws[kk][16+jj];
                acc[0][0] += hv.x*w0; acc[0][1] += hv.x*w1; acc[0][2] += hv.x*w2;
                acc[1][0] += hv.y*w0; acc[1][1] += hv.y*w1; acc[1][2] += hv.y*w2;
                acc[2][0] += hv.z*w0; acc[2][1] += hv.z*w1; acc[2][2] += hv.z*w2;
                acc[3][0] += hv.w*w0; acc[3][1] += hv.w*w1; acc[3][2] += hv.w*w2;
            }
            __syncthreads();
        }

        const float* gt = gi + (size_t)t * BB * H3;
#pragma unroll
        for (int r = 0; r < 4; r++) {
            int b = rg*4 + r;
            size_t gb = (size_t)b * H3;
            float ir  = gt[gb + j];
            float iz  = gt[gb + HH + j];
            float inn = gt[gb + 2*HH + j];
            if (giextra) {
                ir  += giextra[gb + j];
                iz  += giextra[gb + HH + j];
                inn += giextra[gb + 2*HH + j];
            }
            float rr  = 1.f / (1.f + expf(-(ir + acc[r][0] + bh0)));
            float zz  = 1.f / (1.f + expf(-(iz + acc[r][1] + bh1)));
            float nnv = tanhf(inn + rr * (acc[r][2] + bh2));
            float hold = __ldcg(h + (size_t)b*HH + j);
            float hnew = (1.f - zz) * nnv + zz * hold;
            __stcg(hn + (size_t)b*HH + j, hnew);
            if (h2store) h2store[((size_t)t*BB + b)*HH + j] = hnew;
        }
        barno++; grid_bar(barno * RGRID);
    }
}

// ---------------- output assembly ----------------
// out = [outputs (B,L,V) | context (B,H) | mu zeros | log_var zeros]
__global__ void k_out(float* __restrict__ out) {
    long long i = (long long)blockIdx.x * blockDim.x + threadIdx.x;
    const long long NOUT = (long long)BB * LL * VV;
    const long long NC   = (long long)BB * HH;
    if (i < NOUT) {
        int v = (int)(i % VV);
        long long bt = i / VV;
        int t = (int)(bt % LL);
        int b = (int)(bt / LL);
        float val = 0.f;
        if (t > 0) {
            size_t m = (size_t)(t - 1) * BB + b;
            val = g_P[m * VV + v] + g_Pc[(size_t)b * VV + v];
        }
        out[i] = val;
    } else if (i < NOUT + 3*NC) {
        long long r = i - NOUT;
        out[i] = (r < NC) ? g_ctx[r] : 0.f;
    }
}

// ---------------- launch ----------------
extern "C" void kernel_launch(void* const* d_in, const int* in_sizes, int n_in,
                              void* d_out, int out_size) {
    const int*   seq     = (const int*)  d_in[0];
    // d_in[1] = teacher_forcing_ratio (unused by reference math)
    const float* emb_enc = (const float*)d_in[2];
    const float* W_ih_e  = (const float*)d_in[3];
    const float* W_hh_e  = (const float*)d_in[4];
    const float* b_ih_e  = (const float*)d_in[5];
    const float* b_hh_e  = (const float*)d_in[6];
    const float* emb_dec = (const float*)d_in[7];
    const float* W_ih_d  = (const float*)d_in[8];
    const float* W_hh_d  = (const float*)d_in[9];
    const float* b_ih_d  = (const float*)d_in[10];
    const float* b_hh_d  = (const float*)d_in[11];
    const float* fc_W    = (const float*)d_in[12];
    const float* fc_b    = (const float*)d_in[13];

    void* p;
    cudaGetSymbolAddress(&p, g_idx_enc); int*   idx_enc = (int*)p;
    cudaGetSymbolAddress(&p, g_idx_dec); int*   idx_dec = (int*)p;
    cudaGetSymbolAddress(&p, g_gi_enc);  float* gi_enc  = (float*)p;
    cudaGetSymbolAddress(&p, g_gi_dec);  float* gi_dec  = (float*)p;
    cudaGetSymbolAddress(&p, g_gic);     float* gic     = (float*)p;
    cudaGetSymbolAddress(&p, g_hA);      float* hA      = (float*)p;
    cudaGetSymbolAddress(&p, g_hB);      float* hB      = (float*)p;
    cudaGetSymbolAddress(&p, g_ctx);     float* ctx     = (float*)p;
    cudaGetSymbolAddress(&p, g_h2);      float* h2      = (float*)p;
    cudaGetSymbolAddress(&p, g_P);       float* P       = (float*)p;
    cudaGetSymbolAddress(&p, g_Pc);      float* Pc      = (float*)p;

    // 1) gather indices
    k_build_idx<<<(MENC + 255)/256, 256>>>(seq);

    // 2) time-parallel input-gate GEMMs (gathered embeddings)
    k_gemm<<<dim3(H3/64, MENC/128), 256>>>(emb_enc, EE, idx_enc, W_ih_e, EE, 0, b_ih_e, gi_enc, H3, EE, 0);
    k_gemm<<<dim3(H3/64, MDEC/128), 256>>>(emb_dec, EE, idx_dec, W_ih_d, EH, 0, b_ih_d, gi_dec, H3, EE, 0);

    // 3) encoder recurrence (persistent, 256 steps)
    k_reset_bar<<<1, 1>>>();
    k_rec<<<RGRID, 256>>>(W_hh_e, b_hh_e, gi_enc, nullptr, hA, hB, nullptr, LL, 1);

    // 4) context snapshot + context-dependent one-shot GEMMs
    k_copy<<<(BB*HH + 255)/256, 256>>>(ctx, hA, BB*HH);
    k_gemm<<<dim3(H3/64, 1), 256>>>(ctx, HH, nullptr, W_ih_d, EH, EE, nullptr, gic, H3, HH, 0);
    k_gemm<<<dim3(VV/64, 1), 256>>>(ctx, HH, nullptr, fc_W, E2H, EE + HH, nullptr, Pc, VV, HH, 0);

    // 5) decoder recurrence (persistent, 255 steps; h starts at context in hA)
    k_reset_bar<<<1, 1>>>();
    k_rec<<<RGRID, 256>>>(W_hh_d, b_hh_d, gi_dec, gic, hA, hB, h2, LDEC, 0);

    // 6) fc output: e_t part (+bias) then accumulate h2 part
    k_gemm<<<dim3(VV/64, MDEC/128), 256>>>(emb_dec, EE, idx_dec, fc_W, E2H, 0, fc_b, P, VV, EE, 0);
    k_gemm<<<dim3(VV/64, MDEC/128), 256>>>(h2, HH, nullptr, fc_W, E2H, EE, nullptr, P, VV, HH, 1);

    // 7) assemble output tensor (+ context, mu=0, log_var=0, outputs[:,0,:]=0)
    long long total = (long long)BB*LL*VV + 3LL*BB*HH;
    k_out<<<(unsigned)((total + 255)/256), 256>>>((float*)d_out);
}

// round 4
// speedup vs baseline: 1.2320x; 1.2320x over previous
#include <cuda_runtime.h>
#include <cuda_bf16.h>
#include <math.h>
#include <stdint.h>

#define VV   2048
#define EE   512
#define HH   1024
#define BB   128
#define LL   256
#define H3   3072
#define LDEC 255
#define MENC (LL*BB)      /* 32768 */
#define MDEC (LDEC*BB)    /* 32640 */
#define EH   (EE+HH)      /* 1536 */
#define E2H  (EE+2*HH)    /* 2560 */
#define RGRID 128

#define MT_ENC 256
#define MT_DEC 255
#define KC_GI  24          /* 3*512/64  */
#define KC_FC  72          /* 3*1536/64 */
#define NT_GI  24          /* 3072/128  */
#define NT_FC  16          /* 2048/128  */
#define CHB    16384       /* packed chunk: 128 rows x 128B (SW128 image) */
#define NST    4
#define STB    32768
#define SMEMSZ (1024 + NST*STB)

#define SW128(o) ((o) ^ (((o) >> 3) & 0x70))

// ---------------- static scratch ----------------
static __device__ __align__(128) unsigned char g_Xenc_p[(size_t)MT_ENC*KC_GI*CHB];
static __device__ __align__(128) unsigned char g_fcin_p[(size_t)MT_DEC*KC_FC*CHB];
static __device__ __align__(128) unsigned char g_Wihe_p[(size_t)NT_GI*KC_GI*CHB];
static __device__ __align__(128) unsigned char g_Wihd_p[(size_t)NT_GI*KC_GI*CHB];
static __device__ __align__(128) unsigned char g_fcW_p [(size_t)NT_FC*KC_FC*CHB];

static __device__ int   g_idx_enc[MENC];
static __device__ int   g_idx_dec[MDEC];
static __device__ float g_gi_enc[(size_t)MENC*H3];
static __device__ float g_gi_dec[(size_t)MDEC*H3];
static __device__ float g_gic[BB*H3];
static __device__ float g_hA[BB*HH];
static __device__ float g_hB[BB*HH];
static __device__ float g_ctx[BB*HH];
static __device__ float g_Pc[BB*VV];
static __device__ unsigned g_arrive;

// ---------------- PTX helpers (baseline PTX only: no tcgen05/TMEM) ----------------
__device__ __forceinline__ uint32_t s2u(const void* p) {
    uint32_t a;
    asm("{ .reg .u64 t; cvta.to.shared.u64 t, %1; cvt.u32.u64 %0, t; }" : "=r"(a) : "l"(p));
    return a;
}
#define MBAR_INIT(a, c) asm volatile("mbarrier.init.shared.b64 [%0], %1;" :: "r"(a), "r"(c) : "memory")
#define MBAR_EXPECT_TX(a, b) asm volatile("mbarrier.arrive.expect_tx.shared.b64 _, [%0], %1;" :: "r"(a), "r"(b) : "memory")
#define MBAR_ARRIVE(a) asm volatile("mbarrier.arrive.shared.b64 _, [%0];" :: "r"(a) : "memory")

#define MBAR_WAIT(a, p) do { \
    uint32_t _m = (a), _p = (p), _d; \
    asm volatile("{\n\t.reg .pred q;\n\tmbarrier.try_wait.parity.acquire.cta.shared::cta.b64 q, [%1], %2;\n\tselp.b32 %0,1,0,q;\n\t}" \
        : "=r"(_d) : "r"(_m), "r"(_p) : "memory"); \
    if (!_d) { \
        asm volatile("{\n\t.reg .pred Q;\n\tWL_%=:\n\tmbarrier.try_wait.parity.acquire.cta.shared::cta.b64 Q, [%0], %1, 0x989680;\n\t@Q bra.uni WD_%=;\n\tbra.uni WL_%=;\n\tWD_%=:\n\t}" \
            :: "r"(_m), "r"(_p) : "memory"); \
    } \
} while (0)

#define MBAR_WAIT_RLX(a, p) do { \
    uint32_t _m = (a), _p = (p), _d; \
    asm volatile("{\n\t.reg .pred q;\n\tmbarrier.try_wait.parity.relaxed.cta.shared::cta.b64 q, [%1], %2, 0x989680;\n\tselp.b32 %0,1,0,q;\n\t}" \
        : "=r"(_d) : "r"(_m), "r"(_p) : "memory"); \
    if (!_d) { \
        asm volatile("{\n\t.reg .pred Q;\n\tWL_%=:\n\tmbarrier.try_wait.parity.relaxed.cta.shared::cta.b64 Q, [%0], %1, 0x989680;\n\t@Q bra.uni WD_%=;\n\tbra.uni WL_%=;\n\tWD_%=:\n\t}" \
            :: "r"(_m), "r"(_p) : "memory"); \
    } \
} while (0)

__device__ __forceinline__ void bulk_g2s(uint32_t dst, const void* src, uint32_t bytes, uint32_t mbar) {
    asm volatile("cp.async.bulk.shared::cluster.global.mbarrier::complete_tx::bytes [%0], [%1], %2, [%3];"
        :: "r"(dst), "l"(src), "r"(bytes), "r"(mbar) : "memory");
}

#define LDSM_X4(r0, r1, r2, r3, a) \
    asm volatile("ldmatrix.sync.aligned.m8n8.x4.shared.b16 {%0,%1,%2,%3}, [%4];" \
        : "=r"(r0), "=r"(r1), "=r"(r2), "=r"(r3) : "r"(a))

#define MMA16816(d, a0, a1, a2, a3, b0, b1) \
    asm volatile("mma.sync.aligned.m16n8k16.row.col.f32.bf16.bf16.f32 " \
        "{%0,%1,%2,%3}, {%4,%5,%6,%7}, {%8,%9}, {%0,%1,%2,%3};" \
        : "+f"((d)[0]), "+f"((d)[1]), "+f"((d)[2]), "+f"((d)[3]) \
        : "r"(a0), "r"(a1), "r"(a2), "r"(a3), "r"(b0), "r"(b1))

// ---------------- tiny helpers ----------------
__global__ void k_build_idx(const int* __restrict__ seq) {
    int i = blockIdx.x * blockDim.x + threadIdx.x;
    if (i < MENC) { int t = i / BB, b = i % BB; g_idx_enc[i] = seq[b*LL + t]; }
    if (i < MDEC) { int t = i / BB, b = i % BB; g_idx_dec[i] = seq[b*LL + t]; }
}
__global__ void k_reset_bar() { g_arrive = 0u; }
__global__ void k_copy(float* __restrict__ dst, const float* __restrict__ src, int n) {
    int i = blockIdx.x * blockDim.x + threadIdx.x;
    if (i < n) dst[i] = src[i];
}

// ---------------- bf16 split + SW128 packing ----------------
__device__ __forceinline__ void split8(const float* a, uint4& H, uint4& L) {
    unsigned hv[4], lv[4];
#pragma unroll
    for (int j = 0; j < 4; j++) {
        __nv_bfloat16 h0 = __float2bfloat16(a[2*j]),   h1 = __float2bfloat16(a[2*j+1]);
        __nv_bfloat16 l0 = __float2bfloat16(a[2*j]   - __bfloat162float(h0));
        __nv_bfloat16 l1 = __float2bfloat16(a[2*j+1] - __bfloat162float(h1));
        hv[j] = (unsigned)__bfloat16_as_ushort(h0) | ((unsigned)__bfloat16_as_ushort(h1) << 16);
        lv[j] = (unsigned)__bfloat16_as_ushort(l0) | ((unsigned)__bfloat16_as_ushort(l1) << 16);
    }
    H = make_uint4(hv[0], hv[1], hv[2], hv[3]);
    L = make_uint4(lv[0], lv[1], lv[2], lv[3]);
}

// gather embeddings, split hi/lo, write SW128 tile images. K=512 fixed, segs (hi,lo,hi).
__global__ void k_pack_X(const float* __restrict__ emb, const int* __restrict__ idx,
                         unsigned char* __restrict__ dst, int Mrows, int ACH) {
    int i = blockIdx.x * blockDim.x + threadIdx.x;
    int m = i >> 6;
    if (m >= Mrows) return;
    int k = (i & 63) * 8;
    const float* s = emb + (size_t)idx[m] * EE + k;
    float4 f0 = *(const float4*)s, f1 = *(const float4*)(s + 4);
    float a[8] = {f0.x, f0.y, f0.z, f0.w, f1.x, f1.y, f1.z, f1.w};
    uint4 H, L; split8(a, H, L);
    int mt = m >> 7, r = m & 127;
    int sw = SW128(r*128 + (k & 63)*2);
    int c0 = k >> 6;
    size_t tb = (size_t)mt * ACH * CHB;
    *(uint4*)(dst + tb + (size_t)(c0     ) * CHB + sw) = H;
    *(uint4*)(dst + tb + (size_t)(c0 + 8 ) * CHB + sw) = L;
    *(uint4*)(dst + tb + (size_t)(c0 + 16) * CHB + sw) = H;
}

// weights: segs (hi,hi,lo), general Ksrc
__global__ void k_pack_W(const float* __restrict__ W, int ldw, int col0,
                         unsigned char* __restrict__ dst, int Nrows, int Ksrc,
                         int chunkbase, int KCtot) {
    int i = blockIdx.x * blockDim.x + threadIdx.x;
    int Kvec = Ksrc >> 3;
    int n = i / Kvec;
    if (n >= Nrows) return;
    int k = (i - n * Kvec) * 8;
    const float* s = W + (size_t)n * ldw + col0 + k;
    float4 f0 = *(const float4*)s, f1 = *(const float4*)(s + 4);
    float a[8] = {f0.x, f0.y, f0.z, f0.w, f1.x, f1.y, f1.z, f1.w};
    uint4 H, L; split8(a, H, L);
    int nt = n >> 7, r = n & 127;
    int sw = SW128(r*128 + (k & 63)*2);
    int c0 = k >> 6, KS = Ksrc >> 6;
    size_t tb = (size_t)nt * KCtot * CHB;
    *(uint4*)(dst + tb + (size_t)(chunkbase + c0         ) * CHB + sw) = H;
    *(uint4*)(dst + tb + (size_t)(chunkbase + KS + c0    ) * CHB + sw) = H;
    *(uint4*)(dst + tb + (size_t)(chunkbase + 2*KS + c0  ) * CHB + sw) = L;
}

// ---------------- mma.sync bf16 GEMM: C tile 128x128, chunk K=64 ----------------
// 8 warps in 2x4 grid (warp tile 64x32). Producer = thread 0 (bulk copies).
// SMEM: full mbars at sb+8+8s, empty at sb+40+8s, data at sb+1024.
__global__ __launch_bounds__(256, 1)
void k_mmagemm(const unsigned char* __restrict__ Ap, int ACH,
               const unsigned char* __restrict__ Bp, int KC,
               const float* __restrict__ bias, float* __restrict__ C, int ldc,
               const float* __restrict__ Pc, float* __restrict__ outp, int mode) {
    extern __shared__ unsigned char smem[];
    uint32_t sb = s2u(smem);
    int tid = threadIdx.x, wid = tid >> 5, lane = tid & 31;
    int nt = blockIdx.x, mt = blockIdx.y;
    int wm = wid & 1, wn = wid >> 1;

    if (tid == 0) {
        for (int s = 0; s < NST; s++) { MBAR_INIT(sb + 8 + s*8, 1); MBAR_INIT(sb + 40 + s*8, 8); }
    }
    __syncthreads();

    const unsigned char* Ab = Ap + (size_t)mt * ACH * CHB;
    const unsigned char* Bb = Bp + (size_t)nt * KC * CHB;

    if (tid == 0) {
        for (int s = 0; s < NST; s++) {
            MBAR_EXPECT_TX(sb + 8 + s*8, 2*CHB);
            bulk_g2s(sb + 1024 + s*STB,       Ab + (size_t)s*CHB, CHB, sb + 8 + s*8);
            bulk_g2s(sb + 1024 + s*STB + CHB, Bb + (size_t)s*CHB, CHB, sb + 8 + s*8);
        }
    }

    float d[4][4][4];
#pragma unroll
    for (int i = 0; i < 4; i++)
#pragma unroll
        for (int j = 0; j < 4; j++)
#pragma unroll
            for (int q = 0; q < 4; q++) d[i][j][q] = 0.f;

    // Per-lane ldmatrix address components.
    // A frag i: row = wm*64 + i*16 + (lane&15); byte = (ks*32 + (lane>>4)*16) ^ ((row&7)<<4)
    int arow = lane & 15;
    int ahalf = (lane >> 4) * 16;
    int axm = (arow & 7) << 4;
    uint32_t aRow128[4];
#pragma unroll
    for (int i = 0; i < 4; i++) aRow128[i] = (uint32_t)(wm*64 + i*16 + arow) * 128;
    // B x4 over nfrags {2q, 2q+1}: g = lane>>3; n = wn*32 + q*16 + (g>>1)*8 + (lane&7); kadd = (g&1)*16
    int bg = lane >> 3;
    int bn7 = lane & 7;
    int bxm = bn7 << 4;
    int bkadd = (bg & 1) * 16;
    uint32_t bRow128[2];
#pragma unroll
    for (int q = 0; q < 2; q++) bRow128[q] = (uint32_t)(wn*32 + q*16 + (bg>>1)*8 + bn7) * 128;

    for (int kc = 0; kc < KC; kc++) {
        int s = kc & (NST - 1);
        int ph = (kc / NST) & 1;
        MBAR_WAIT(sb + 8 + s*8, ph);
        uint32_t Abase = sb + 1024 + s*STB;
        uint32_t Bbase = Abase + CHB;
#pragma unroll
        for (int ks = 0; ks < 4; ks++) {
            int kb = ks * 32;
            uint32_t afr[4][4], bfr[2][4];
#pragma unroll
            for (int i = 0; i < 4; i++) {
                uint32_t addr = Abase + aRow128[i] + (uint32_t)((kb + ahalf) ^ axm);
                LDSM_X4(afr[i][0], afr[i][1], afr[i][2], afr[i][3], addr);
            }
#pragma unroll
            for (int q = 0; q < 2; q++) {
                uint32_t addr = Bbase + bRow128[q] + (uint32_t)((kb + bkadd) ^ bxm);
                LDSM_X4(bfr[q][0], bfr[q][1], bfr[q][2], bfr[q][3], addr);
            }
#pragma unroll
            for (int i = 0; i < 4; i++)
#pragma unroll
                for (int j = 0; j < 4; j++)
                    MMA16816(d[i][j], afr[i][0], afr[i][1], afr[i][2], afr[i][3],
                             bfr[j>>1][(j&1)*2], bfr[j>>1][(j&1)*2 + 1]);
        }
        __syncwarp();
        if (lane == 0) MBAR_ARRIVE(sb + 40 + s*8);
        if (tid == 0 && kc + NST < KC) {
            MBAR_WAIT_RLX(sb + 40 + s*8, (kc / NST) & 1);
            MBAR_EXPECT_TX(sb + 8 + s*8, 2*CHB);
            bulk_g2s(sb + 1024 + s*STB,       Ab + (size_t)(kc+NST)*CHB, CHB, sb + 8 + s*8);
            bulk_g2s(sb + 1024 + s*STB + CHB, Bb + (size_t)(kc+NST)*CHB, CHB, sb + 8 + s*8);
        }
    }

    // epilogue
    int lr = lane >> 2;          // row within 8
    int lc = (lane & 3) * 2;     // col pair
#pragma unroll
    for (int i = 0; i < 4; i++) {
        int r0 = wm*64 + i*16 + lr;
#pragma unroll
        for (int j = 0; j < 4; j++) {
            int c = nt*128 + wn*32 + j*8 + lc;
            if (mode == 0) {
                float2 bv = *(const float2*)(bias + c);
                float* cp0 = C + (size_t)(mt*128 + r0) * ldc + c;
                float* cp1 = C + (size_t)(mt*128 + r0 + 8) * ldc + c;
                *(float2*)cp0 = make_float2(d[i][j][0] + bv.x, d[i][j][1] + bv.y);
                *(float2*)cp1 = make_float2(d[i][j][2] + bv.x, d[i][j][3] + bv.y);
            } else {
                float2 p0 = *(const float2*)(Pc + (size_t)r0 * VV + c);
                float2 p1 = *(const float2*)(Pc + (size_t)(r0 + 8) * VV + c);
                float* op0 = outp + ((size_t)r0 * LL + (mt + 1)) * VV + c;
                float* op1 = outp + ((size_t)(r0 + 8) * LL + (mt + 1)) * VV + c;
                *(float2*)op0 = make_float2(d[i][j][0] + p0.x, d[i][j][1] + p0.y);
                *(float2*)op1 = make_float2(d[i][j][2] + p1.x, d[i][j][3] + p1.y);
            }
        }
    }
}

// ---------------- small fp32 GEMM (context-only one-shots) ----------------
__global__ __launch_bounds__(256) void k_gemm(
    const float* __restrict__ A, int lda, const int* __restrict__ idx,
    const float* __restrict__ Bw, int ldb, int bofs,
    const float* __restrict__ bias,
    float* __restrict__ C, int N, int K, int accumulate)
{
    __shared__ float As[16][132];
    __shared__ float Bs[16][68];
    const int m0 = blockIdx.y * 128;
    const int n0 = blockIdx.x * 64;
    const int tid = threadIdx.x;
    const int rg = tid >> 4, cg = tid & 15;
    float acc[8][4];
#pragma unroll
    for (int i = 0; i < 8; i++)
#pragma unroll
        for (int j = 0; j < 4; j++) acc[i][j] = 0.f;
    const int r0 = tid >> 2, r1 = r0 + 64;
    const int kq0 = (tid & 3) * 4;
    const size_t aoff0 = (size_t)(idx ? idx[m0+r0] : m0+r0) * lda;
    const size_t aoff1 = (size_t)(idx ? idx[m0+r1] : m0+r1) * lda;
    const size_t boff  = (size_t)(n0 + r0) * ldb + bofs;
    for (int k0 = 0; k0 < K; k0 += 16) {
        float4 va0 = *reinterpret_cast<const float4*>(A + aoff0 + k0 + kq0);
        float4 va1 = *reinterpret_cast<const float4*>(A + aoff1 + k0 + kq0);
        float4 vb  = *reinterpret_cast<const float4*>(Bw + boff + k0 + kq0);
        As[kq0+0][r0] = va0.x; As[kq0+1][r0] = va0.y; As[kq0+2][r0] = va0.z; As[kq0+3][r0] = va0.w;
        As[kq0+0][r1] = va1.x; As[kq0+1][r1] = va1.y; As[kq0+2][r1] = va1.z; As[kq0+3][r1] = va1.w;
        Bs[kq0+0][r0] = vb.x;  Bs[kq0+1][r0] = vb.y;  Bs[kq0+2][r0] = vb.z;  Bs[kq0+3][r0] = vb.w;
        __syncthreads();
#pragma unroll
        for (int kk = 0; kk < 16; kk++) {
            float4 a0 = *reinterpret_cast<const float4*>(&As[kk][rg*8]);
            float4 a1 = *reinterpret_cast<const float4*>(&As[kk][rg*8+4]);
            float4 b  = *reinterpret_cast<const float4*>(&Bs[kk][cg*4]);
            float av[8] = {a0.x,a0.y,a0.z,a0.w,a1.x,a1.y,a1.z,a1.w};
            float bv[4] = {b.x,b.y,b.z,b.w};
#pragma unroll
            for (int i = 0; i < 8; i++)
#pragma unroll
                for (int j = 0; j < 4; j++) acc[i][j] += av[i]*bv[j];
        }
        __syncthreads();
    }
    float4 bb = make_float4(0.f,0.f,0.f,0.f);
    if (bias) bb = *reinterpret_cast<const float4*>(bias + n0 + cg*4);
#pragma unroll
    for (int i = 0; i < 8; i++) {
        float* cp = C + (size_t)(m0 + rg*8 + i) * N + n0 + cg*4;
        float4 v = make_float4(acc[i][0]+bb.x, acc[i][1]+bb.y, acc[i][2]+bb.z, acc[i][3]+bb.w);
        if (accumulate) {
            float4 p = *reinterpret_cast<const float4*>(cp);
            v.x += p.x; v.y += p.y; v.z += p.z; v.w += p.w;
        }
        *reinterpret_cast<float4*>(cp) = v;
    }
}

// ---------------- grid barrier ----------------
__device__ __forceinline__ void grid_bar(unsigned want) {
    __threadfence();
    __syncthreads();
    if (threadIdx.x == 0) {
        atomicAdd(&g_arrive, 1u);
        volatile unsigned* p = &g_arrive;
        while (*p < want) { }
    }
    __syncthreads();
}

// ---------------- persistent GRU recurrence ----------------
__global__ __launch_bounds__(256) void k_rec(
    const float* __restrict__ Whh, const float* __restrict__ bhh,
    const float* __restrict__ gi, const float* __restrict__ giextra,
    float* __restrict__ h0buf, float* __restrict__ h1buf,
    unsigned char* __restrict__ h2pack,
    int T, int initzero)
{
    __shared__ float hs[16][132];
    __shared__ float Ws[16][28];
    const int tid = threadIdx.x;
    const int bid = blockIdx.x;
    const int j0  = bid * 8;
    const int rg  = tid >> 3;
    const int jj  = tid & 7;
    const int j   = j0 + jj;

    unsigned barno = 0;
    if (initzero) {
        for (int i = bid*256 + tid; i < BB*HH; i += RGRID*256) h0buf[i] = 0.f;
    }
    barno++; grid_bar(barno * RGRID);

    const int wc  = tid >> 2;
    const int wkq = (tid & 3) * 4;
    size_t woff = 0;
    if (tid < 96) {
        int g = wc >> 3, j2 = wc & 7;
        woff = (size_t)(g*HH + j0 + j2) * HH + wkq;
    }
    const int hrow = tid >> 2;
    const int hkq  = (tid & 3) * 4;
    const float bh0 = bhh[j], bh1 = bhh[HH + j], bh2 = bhh[2*HH + j];

    for (int t = 0; t < T; t++) {
        const float* __restrict__ h  = (t & 1) ? h1buf : h0buf;
        float*       __restrict__ hn = (t & 1) ? h0buf : h1buf;
        float acc[4][3];
#pragma unroll
        for (int r = 0; r < 4; r++) { acc[r][0]=0.f; acc[r][1]=0.f; acc[r][2]=0.f; }

        for (int k0 = 0; k0 < HH; k0 += 16) {
            float4 v0 = __ldcg(reinterpret_cast<const float4*>(h + (size_t)hrow*HH + k0 + hkq));
            float4 v1 = __ldcg(reinterpret_cast<const float4*>(h + (size_t)(hrow+64)*HH + k0 + hkq));
            float4 vw = make_float4(0.f,0.f,0.f,0.f);
            if (tid < 96) vw = *reinterpret_cast<const float4*>(Whh + woff + k0);
            hs[hkq+0][hrow]    = v0.x; hs[hkq+1][hrow]    = v0.y; hs[hkq+2][hrow]    = v0.z; hs[hkq+3][hrow]    = v0.w;
            hs[hkq+0][hrow+64] = v1.x; hs[hkq+1][hrow+64] = v1.y; hs[hkq+2][hrow+64] = v1.z; hs[hkq+3][hrow+64] = v1.w;
            if (tid < 96) { Ws[wkq+0][wc] = vw.x; Ws[wkq+1][wc] = vw.y; Ws[wkq+2][wc] = vw.z; Ws[wkq+3][wc] = vw.w; }
            __syncthreads();
#pragma unroll
            for (int kk = 0; kk < 16; kk++) {
                float4 hv = *reinterpret_cast<const float4*>(&hs[kk][rg*4]);
                float w0 = Ws[kk][jj], w1 = Ws[kk][8+jj], w2 = Ws[kk][16+jj];
                acc[0][0] += hv.x*w0; acc[0][1] += hv.x*w1; acc[0][2] += hv.x*w2;
                acc[1][0] += hv.y*w0; acc[1][1] += hv.y*w1; acc[1][2] += hv.y*w2;
                acc[2][0] += hv.z*w0; acc[2][1] += hv.z*w1; acc[2][2] += hv.z*w2;
                acc[3][0] += hv.w*w0; acc[3][1] += hv.w*w1; acc[3][2] += hv.w*w2;
            }
            __syncthreads();
        }

        const float* gt = gi + (size_t)t * BB * H3;
#pragma unroll
        for (int r = 0; r < 4; r++) {
            int b = rg*4 + r;
            size_t gb = (size_t)b * H3;
            float ir  = gt[gb + j];
            float iz  = gt[gb + HH + j];
            float inn = gt[gb + 2*HH + j];
            if (giextra) {
                ir  += giextra[gb + j];
                iz  += giextra[gb + HH + j];
                inn += giextra[gb + 2*HH + j];
            }
            float rr  = 1.f / (1.f + expf(-(ir + acc[r][0] + bh0)));
            float zz  = 1.f / (1.f + expf(-(iz + acc[r][1] + bh1)));
            float nnv = tanhf(inn + rr * (acc[r][2] + bh2));
            float hold = __ldcg(h + (size_t)b*HH + j);
            float hnew = (1.f - zz) * nnv + zz * hold;
            __stcg(hn + (size_t)b*HH + j, hnew);
            if (h2pack) {
                __nv_bfloat16 hb = __float2bfloat16(hnew);
                __nv_bfloat16 lb = __float2bfloat16(hnew - __bfloat162float(hb));
                int c = j >> 6;
                int sw = SW128(b*128 + (j & 63)*2);
                size_t tb2 = (size_t)t * KC_FC * CHB;
                *(__nv_bfloat16*)(h2pack + tb2 + (size_t)(24 + c)*CHB + sw) = hb;
                *(__nv_bfloat16*)(h2pack + tb2 + (size_t)(40 + c)*CHB + sw) = lb;
                *(__nv_bfloat16*)(h2pack + tb2 + (size_t)(56 + c)*CHB + sw) = hb;
            }
        }
        barno++; grid_bar(barno * RGRID);
    }
}

// ---------------- small output pieces: row t=0 zeros, context, mu/logvar ----------------
__global__ void k_out_small(float* __restrict__ out) {
    int i = blockIdx.x * blockDim.x + threadIdx.x;
    const size_t NOUT = (size_t)BB * LL * VV;
    if (i < BB * VV) {
        int b = i / VV, v = i % VV;
        out[(size_t)b * LL * VV + v] = 0.f;
    }
    if (i < 3 * BB * HH) {
        out[NOUT + i] = (i < BB * HH) ? g_ctx[i] : 0.f;
    }
}

// ---------------- launch ----------------
extern "C" void kernel_launch(void* const* d_in, const int* in_sizes, int n_in,
                              void* d_out, int out_size) {
    const int*   seq     = (const int*)  d_in[0];
    const float* emb_enc = (const float*)d_in[2];
    const float* W_ih_e  = (const float*)d_in[3];
    const float* W_hh_e  = (const float*)d_in[4];
    const float* b_ih_e  = (const float*)d_in[5];
    const float* b_hh_e  = (const float*)d_in[6];
    const float* emb_dec = (const float*)d_in[7];
    const float* W_ih_d  = (const float*)d_in[8];
    const float* W_hh_d  = (const float*)d_in[9];
    const float* b_ih_d  = (const float*)d_in[10];
    const float* b_hh_d  = (const float*)d_in[11];
    const float* fc_W    = (const float*)d_in[12];
    const float* fc_b    = (const float*)d_in[13];

    void* p;
    cudaGetSymbolAddress(&p, g_idx_enc); int* idx_enc = (int*)p;
    cudaGetSymbolAddress(&p, g_idx_dec); int* idx_dec = (int*)p;
    cudaGetSymbolAddress(&p, g_gi_enc);  float* gi_enc = (float*)p;
    cudaGetSymbolAddress(&p, g_gi_dec);  float* gi_dec = (float*)p;
    cudaGetSymbolAddress(&p, g_gic);     float* gic = (float*)p;
    cudaGetSymbolAddress(&p, g_hA);      float* hA = (float*)p;
    cudaGetSymbolAddress(&p, g_hB);      float* hB = (float*)p;
    cudaGetSymbolAddress(&p, g_ctx);     float* ctx = (float*)p;
    cudaGetSymbolAddress(&p, g_Pc);      float* Pc = (float*)p;
    cudaGetSymbolAddress(&p, g_Xenc_p);  unsigned char* Xenc_p = (unsigned char*)p;
    cudaGetSymbolAddress(&p, g_fcin_p);  unsigned char* fcin_p = (unsigned char*)p;
    cudaGetSymbolAddress(&p, g_Wihe_p);  unsigned char* Wihe_p = (unsigned char*)p;
    cudaGetSymbolAddress(&p, g_Wihd_p);  unsigned char* Wihd_p = (unsigned char*)p;
    cudaGetSymbolAddress(&p, g_fcW_p);   unsigned char* fcW_p = (unsigned char*)p;

    cudaFuncSetAttribute(k_mmagemm, cudaFuncAttributeMaxDynamicSharedMemorySize, SMEMSZ);

    // 1) gather indices + packing (bf16 hi/lo, SW128 tile images)
    k_build_idx<<<(MENC + 255)/256, 256>>>(seq);
    k_pack_X<<<(MENC*64 + 255)/256, 256>>>(emb_enc, idx_enc, Xenc_p, MENC, KC_GI);
    k_pack_X<<<(MDEC*64 + 255)/256, 256>>>(emb_dec, idx_dec, fcin_p, MDEC, KC_FC);
    k_pack_W<<<(H3*64 + 255)/256, 256>>>(W_ih_e, EE,  0,  Wihe_p, H3, EE, 0,  KC_GI);
    k_pack_W<<<(H3*64 + 255)/256, 256>>>(W_ih_d, EH,  0,  Wihd_p, H3, EE, 0,  KC_GI);
    k_pack_W<<<(VV*64 + 255)/256, 256>>>(fc_W,   E2H, 0,  fcW_p,  VV, EE, 0,  KC_FC);
    k_pack_W<<<(VV*128 + 255)/256, 256>>>(fc_W,  E2H, EE, fcW_p,  VV, HH, 24, KC_FC);

    // 2) tensor-core (mma.sync) input-gate GEMMs
    k_mmagemm<<<dim3(NT_GI, MT_ENC), 256, SMEMSZ>>>(Xenc_p, KC_GI, Wihe_p, KC_GI, b_ih_e, gi_enc, H3, nullptr, nullptr, 0);
    k_mmagemm<<<dim3(NT_GI, MT_DEC), 256, SMEMSZ>>>(fcin_p, KC_FC, Wihd_p, KC_GI, b_ih_d, gi_dec, H3, nullptr, nullptr, 0);

    // 3) encoder recurrence
    k_reset_bar<<<1, 1>>>();
    k_rec<<<RGRID, 256>>>(W_hh_e, b_hh_e, gi_enc, nullptr, hA, hB, nullptr, LL, 1);

    // 4) context one-shots (small fp32 GEMMs)
    k_copy<<<(BB*HH + 255)/256, 256>>>(ctx, hA, BB*HH);
    k_gemm<<<dim3(H3/64, 1), 256>>>(ctx, HH, nullptr, W_ih_d, EH, EE, nullptr, gic, H3, HH, 0);
    k_gemm<<<dim3(VV/64, 1), 256>>>(ctx, HH, nullptr, fc_W, E2H, EE + HH, fc_b, Pc, VV, HH, 0);

    // 5) decoder recurrence (packs h2 hi/lo into fcin_p chunks 24..71)
    k_reset_bar<<<1, 1>>>();
    k_rec<<<RGRID, 256>>>(W_hh_d, b_hh_d, gi_dec, gic, hA, hB, fcin_p, LDEC, 0);

    // 6) fused fc GEMM: [e_t | h2] @ fc_W^T, epilogue adds Pc(+fc_b) and writes d_out
    k_mmagemm<<<dim3(NT_FC, MT_DEC), 256, SMEMSZ>>>(fcin_p, KC_FC, fcW_p, KC_FC, nullptr, nullptr, 0, Pc, (float*)d_out, 1);

    // 7) small output pieces
    k_out_small<<<(3*BB*HH + 255)/256, 256>>>((float*)d_out);
}

// round 5
// speedup vs baseline: 2.4419x; 1.9820x over previous
#include <cuda_runtime.h>
#include <cuda_bf16.h>
#include <math.h>
#include <stdint.h>

#define VV   2048
#define EE   512
#define HH   1024
#define BB   128
#define LL   256
#define H3   3072
#define LDEC 255
#define MENC (LL*BB)
#define MDEC (LDEC*BB)
#define EH   (EE+HH)
#define E2H  (EE+2*HH)
#define RGRID 128

#define MT_ENC 256
#define MT_DEC 255
#define KC_GI  24
#define KC_FC  72
#define NT_GI  24
#define NT_FC  16
#define CHB    16384
#define NST    4
#define STB    32768
#define SMEMSZ (1024 + NST*STB)

/* recurrence kernel constants */
#define RCH      16384                 /* A chunk: 128 rows x 128B */
#define RNCH     32                    /* chunks per h image: 16 hi + 16 lo */
#define IMGB     ((size_t)RNCH*RCH)    /* 512 KB per image */
#define RW_BYTES 98304                 /* per-block W slice: 32 chunks x 24 rows x 128B */
#define RSM      (1024 + NST*RCH + RW_BYTES)

#define SW128(o) ((o) ^ (((o) >> 3) & 0x70))

// ---------------- static scratch ----------------
static __device__ __align__(128) unsigned char g_Xenc_p[(size_t)MT_ENC*KC_GI*CHB];
static __device__ __align__(128) unsigned char g_fcin_p[(size_t)MT_DEC*KC_FC*CHB];
static __device__ __align__(128) unsigned char g_Wihe_p[(size_t)NT_GI*KC_GI*CHB];
static __device__ __align__(128) unsigned char g_Wihd_p[(size_t)NT_GI*KC_GI*CHB];
static __device__ __align__(128) unsigned char g_fcW_p [(size_t)NT_FC*KC_FC*CHB];
static __device__ __align__(128) unsigned char g_WhhE_img[(size_t)RGRID*RW_BYTES];
static __device__ __align__(128) unsigned char g_WhhD_img[(size_t)RGRID*RW_BYTES];
static __device__ __align__(128) unsigned char g_hImg[2*IMGB];

static __device__ int   g_idx_enc[MENC];
static __device__ int   g_idx_dec[MDEC];
static __device__ float g_gi_enc[(size_t)MENC*H3];
static __device__ float g_gi_dec[(size_t)MDEC*H3];
static __device__ float g_gic[BB*H3];
static __device__ float g_ctx[BB*HH];
static __device__ float g_Pc[BB*VV];
static __device__ unsigned g_arrive;

// ---------------- PTX helpers (baseline PTX only) ----------------
__device__ __forceinline__ uint32_t s2u(const void* p) {
    uint32_t a;
    asm("{ .reg .u64 t; cvta.to.shared.u64 t, %1; cvt.u32.u64 %0, t; }" : "=r"(a) : "l"(p));
    return a;
}
#define MBAR_INIT(a, c) asm volatile("mbarrier.init.shared.b64 [%0], %1;" :: "r"(a), "r"(c) : "memory")
#define MBAR_EXPECT_TX(a, b) asm volatile("mbarrier.arrive.expect_tx.shared.b64 _, [%0], %1;" :: "r"(a), "r"(b) : "memory")
#define MBAR_ARRIVE(a) asm volatile("mbarrier.arrive.shared.b64 _, [%0];" :: "r"(a) : "memory")

#define MBAR_WAIT(a, p) do { \
    uint32_t _m = (a), _p = (p), _d; \
    asm volatile("{\n\t.reg .pred q;\n\tmbarrier.try_wait.parity.acquire.cta.shared::cta.b64 q, [%1], %2;\n\tselp.b32 %0,1,0,q;\n\t}" \
        : "=r"(_d) : "r"(_m), "r"(_p) : "memory"); \
    if (!_d) { \
        asm volatile("{\n\t.reg .pred Q;\n\tWL_%=:\n\tmbarrier.try_wait.parity.acquire.cta.shared::cta.b64 Q, [%0], %1, 0x989680;\n\t@Q bra.uni WD_%=;\n\tbra.uni WL_%=;\n\tWD_%=:\n\t}" \
            :: "r"(_m), "r"(_p) : "memory"); \
    } \
} while (0)

#define MBAR_WAIT_RLX(a, p) do { \
    uint32_t _m = (a), _p = (p), _d; \
    asm volatile("{\n\t.reg .pred q;\n\tmbarrier.try_wait.parity.relaxed.cta.shared::cta.b64 q, [%1], %2, 0x989680;\n\tselp.b32 %0,1,0,q;\n\t}" \
        : "=r"(_d) : "r"(_m), "r"(_p) : "memory"); \
    if (!_d) { \
        asm volatile("{\n\t.reg .pred Q;\n\tWL_%=:\n\tmbarrier.try_wait.parity.relaxed.cta.shared::cta.b64 Q, [%0], %1, 0x989680;\n\t@Q bra.uni WD_%=;\n\tbra.uni WL_%=;\n\tWD_%=:\n\t}" \
            :: "r"(_m), "r"(_p) : "memory"); \
    } \
} while (0)

__device__ __forceinline__ void bulk_g2s(uint32_t dst, const void* src, uint32_t bytes, uint32_t mbar) {
    asm volatile("cp.async.bulk.shared::cluster.global.mbarrier::complete_tx::bytes [%0], [%1], %2, [%3];"
        :: "r"(dst), "l"(src), "r"(bytes), "r"(mbar) : "memory");
}

#define LDSM_X4(r0, r1, r2, r3, a) \
    asm volatile("ldmatrix.sync.aligned.m8n8.x4.shared.b16 {%0,%1,%2,%3}, [%4];" \
        : "=r"(r0), "=r"(r1), "=r"(r2), "=r"(r3) : "r"(a))
#define LDSM_X2(r0, r1, a) \
    asm volatile("ldmatrix.sync.aligned.m8n8.x2.shared.b16 {%0,%1}, [%2];" \
        : "=r"(r0), "=r"(r1) : "r"(a))

#define MMA16816(d, a0, a1, a2, a3, b0, b1) \
    asm volatile("mma.sync.aligned.m16n8k16.row.col.f32.bf16.bf16.f32 " \
        "{%0,%1,%2,%3}, {%4,%5,%6,%7}, {%8,%9}, {%0,%1,%2,%3};" \
        : "+f"((d)[0]), "+f"((d)[1]), "+f"((d)[2]), "+f"((d)[3]) \
        : "r"(a0), "r"(a1), "r"(a2), "r"(a3), "r"(b0), "r"(b1))

// ---------------- tiny helpers ----------------
__global__ void k_build_idx(const int* __restrict__ seq) {
    int i = blockIdx.x * blockDim.x + threadIdx.x;
    if (i < MENC) { int t = i / BB, b = i % BB; g_idx_enc[i] = seq[b*LL + t]; }
    if (i < MDEC) { int t = i / BB, b = i % BB; g_idx_dec[i] = seq[b*LL + t]; }
}
__global__ void k_reset_bar() { g_arrive = 0u; }

// ---------------- bf16 split + SW128 packing ----------------
__device__ __forceinline__ void split8(const float* a, uint4& H, uint4& L) {
    unsigned hv[4], lv[4];
#pragma unroll
    for (int j = 0; j < 4; j++) {
        __nv_bfloat16 h0 = __float2bfloat16(a[2*j]),   h1 = __float2bfloat16(a[2*j+1]);
        __nv_bfloat16 l0 = __float2bfloat16(a[2*j]   - __bfloat162float(h0));
        __nv_bfloat16 l1 = __float2bfloat16(a[2*j+1] - __bfloat162float(h1));
        hv[j] = (unsigned)__bfloat16_as_ushort(h0) | ((unsigned)__bfloat16_as_ushort(h1) << 16);
        lv[j] = (unsigned)__bfloat16_as_ushort(l0) | ((unsigned)__bfloat16_as_ushort(l1) << 16);
    }
    H = make_uint4(hv[0], hv[1], hv[2], hv[3]);
    L = make_uint4(lv[0], lv[1], lv[2], lv[3]);
}

__global__ void k_pack_X(const float* __restrict__ emb, const int* __restrict__ idx,
                         unsigned char* __restrict__ dst, int Mrows, int ACH) {
    int i = blockIdx.x * blockDim.x + threadIdx.x;
    int m = i >> 6;
    if (m >= Mrows) return;
    int k = (i & 63) * 8;
    const float* s = emb + (size_t)idx[m] * EE + k;
    float4 f0 = *(const float4*)s, f1 = *(const float4*)(s + 4);
    float a[8] = {f0.x, f0.y, f0.z, f0.w, f1.x, f1.y, f1.z, f1.w};
    uint4 H, L; split8(a, H, L);
    int mt = m >> 7, r = m & 127;
    int sw = SW128(r*128 + (k & 63)*2);
    int c0 = k >> 6;
    size_t tb = (size_t)mt * ACH * CHB;
    *(uint4*)(dst + tb + (size_t)(c0     ) * CHB + sw) = H;
    *(uint4*)(dst + tb + (size_t)(c0 + 8 ) * CHB + sw) = L;
    *(uint4*)(dst + tb + (size_t)(c0 + 16) * CHB + sw) = H;
}

__global__ void k_pack_W(const float* __restrict__ W, int ldw, int col0,
                         unsigned char* __restrict__ dst, int Nrows, int Ksrc,
                         int chunkbase, int KCtot) {
    int i = blockIdx.x * blockDim.x + threadIdx.x;
    int Kvec = Ksrc >> 3;
    int n = i / Kvec;
    if (n >= Nrows) return;
    int k = (i - n * Kvec) * 8;
    const float* s = W + (size_t)n * ldw + col0 + k;
    float4 f0 = *(const float4*)s, f1 = *(const float4*)(s + 4);
    float a[8] = {f0.x, f0.y, f0.z, f0.w, f1.x, f1.y, f1.z, f1.w};
    uint4 H, L; split8(a, H, L);
    int nt = n >> 7, r = n & 127;
    int sw = SW128(r*128 + (k & 63)*2);
    int c0 = k >> 6, KS = Ksrc >> 6;
    size_t tb = (size_t)nt * KCtot * CHB;
    *(uint4*)(dst + tb + (size_t)(chunkbase + c0         ) * CHB + sw) = H;
    *(uint4*)(dst + tb + (size_t)(chunkbase + KS + c0    ) * CHB + sw) = H;
    *(uint4*)(dst + tb + (size_t)(chunkbase + 2*KS + c0  ) * CHB + sw) = L;
}

// Whh image: per block slice [32 chunks (16 Wh, 16 Wl)][24 rows x 128B SW128]
__global__ void k_pack_Whh(const float* __restrict__ Whh, unsigned char* __restrict__ img) {
    int i = blockIdx.x * blockDim.x + threadIdx.x;
    if (i >= H3 * (HH/8)) return;
    int n = i >> 7;              // N row 0..3071
    int k = (i & 127) * 8;       // k 0..1023
    int g = n >> 10, hcol = n & 1023;
    int blk = hcol >> 3, jj = hcol & 7;
    int rr = g*8 + jj;
    const float* s = Whh + (size_t)n * HH + k;
    float4 f0 = *(const float4*)s, f1 = *(const float4*)(s + 4);
    float a[8] = {f0.x, f0.y, f0.z, f0.w, f1.x, f1.y, f1.z, f1.w};
    uint4 H, L; split8(a, H, L);
    unsigned char* base = img + (size_t)blk * RW_BYTES;
    int sw = SW128(rr*128 + (k & 63)*2);
    *(uint4*)(base + (size_t)(k >> 6) * 3072 + sw) = H;
    *(uint4*)(base + (size_t)(16 + (k >> 6)) * 3072 + sw) = L;
}

// ---------------- mma.sync bf16 GEMM with dedicated producer warp ----------------
// 288 threads: warps 0-7 compute (2x4 warp grid, 64x32 warp tile), warp 8 = producer.
__global__ __launch_bounds__(288, 1)
void k_mmagemm(const unsigned char* __restrict__ Ap, int ACH,
               const unsigned char* __restrict__ Bp, int KC,
               const float* __restrict__ bias, float* __restrict__ C, int ldc,
               const float* __restrict__ Pc, float* __restrict__ outp, int mode) {
    extern __shared__ unsigned char smem[];
    uint32_t sb = s2u(smem);
    int tid = threadIdx.x, wid = tid >> 5, lane = tid & 31;
    int nt = blockIdx.x, mt = blockIdx.y;

    if (tid == 0) {
        for (int s = 0; s < NST; s++) { MBAR_INIT(sb + 8 + s*8, 1); MBAR_INIT(sb + 40 + s*8, 8); }
    }
    __syncthreads();

    const unsigned char* Ab = Ap + (size_t)mt * ACH * CHB;
    const unsigned char* Bb = Bp + (size_t)nt * KC * CHB;

    if (wid == 8) {
        if (lane == 0) {
            for (int kc = 0; kc < KC; kc++) {
                int s = kc & (NST - 1);
                int eph = (((kc >> 2) & 1)) ^ 1;
                MBAR_WAIT_RLX(sb + 40 + s*8, eph);
                MBAR_EXPECT_TX(sb + 8 + s*8, 2*CHB);
                bulk_g2s(sb + 1024 + s*STB,       Ab + (size_t)kc*CHB, CHB, sb + 8 + s*8);
                bulk_g2s(sb + 1024 + s*STB + CHB, Bb + (size_t)kc*CHB, CHB, sb + 8 + s*8);
            }
        }
        return;
    }

    int wm = wid & 1, wn = wid >> 1;
    float d[4][4][4];
#pragma unroll
    for (int i = 0; i < 4; i++)
#pragma unroll
        for (int j = 0; j < 4; j++)
#pragma unroll
            for (int q = 0; q < 4; q++) d[i][j][q] = 0.f;

    int arow = lane & 15;
    int ahalf = (lane >> 4) * 16;
    int axm = (arow & 7) << 4;
    uint32_t aRow128[4];
#pragma unroll
    for (int i = 0; i < 4; i++) aRow128[i] = (uint32_t)(wm*64 + i*16 + arow) * 128;
    int bg = lane >> 3;
    int bn7 = lane & 7;
    int bxm = bn7 << 4;
    int bkadd = (bg & 1) * 16;
    uint32_t bRow128[2];
#pragma unroll
    for (int q = 0; q < 2; q++) bRow128[q] = (uint32_t)(wn*32 + q*16 + (bg>>1)*8 + bn7) * 128;

    for (int kc = 0; kc < KC; kc++) {
        int s = kc & (NST - 1);
        int ph = (kc >> 2) & 1;
        MBAR_WAIT(sb + 8 + s*8, ph);
        uint32_t Abase = sb + 1024 + s*STB;
        uint32_t Bbase = Abase + CHB;
#pragma unroll
        for (int ks = 0; ks < 4; ks++) {
            int kb = ks * 32;
            uint32_t afr[4][4], bfr[2][4];
#pragma unroll
            for (int i = 0; i < 4; i++) {
                uint32_t addr = Abase + aRow128[i] + (uint32_t)((kb + ahalf) ^ axm);
                LDSM_X4(afr[i][0], afr[i][1], afr[i][2], afr[i][3], addr);
            }
#pragma unroll
            for (int q = 0; q < 2; q++) {
                uint32_t addr = Bbase + bRow128[q] + (uint32_t)((kb + bkadd) ^ bxm);
                LDSM_X4(bfr[q][0], bfr[q][1], bfr[q][2], bfr[q][3], addr);
            }
#pragma unroll
            for (int i = 0; i < 4; i++)
#pragma unroll
                for (int j = 0; j < 4; j++)
                    MMA16816(d[i][j], afr[i][0], afr[i][1], afr[i][2], afr[i][3],
                             bfr[j>>1][(j&1)*2], bfr[j>>1][(j&1)*2 + 1]);
        }
        __syncwarp();
        if (lane == 0) MBAR_ARRIVE(sb + 40 + s*8);
    }

    int lr = lane >> 2;
    int lc = (lane & 3) * 2;
#pragma unroll
    for (int i = 0; i < 4; i++) {
        int r0 = wm*64 + i*16 + lr;
#pragma unroll
        for (int j = 0; j < 4; j++) {
            int c = nt*128 + wn*32 + j*8 + lc;
            if (mode == 0) {
                float2 bv = *(const float2*)(bias + c);
                float* cp0 = C + (size_t)(mt*128 + r0) * ldc + c;
                float* cp1 = C + (size_t)(mt*128 + r0 + 8) * ldc + c;
                *(float2*)cp0 = make_float2(d[i][j][0] + bv.x, d[i][j][1] + bv.y);
                *(float2*)cp1 = make_float2(d[i][j][2] + bv.x, d[i][j][3] + bv.y);
            } else {
                float2 p0 = *(const float2*)(Pc + (size_t)r0 * VV + c);
                float2 p1 = *(const float2*)(Pc + (size_t)(r0 + 8) * VV + c);
                float* op0 = outp + ((size_t)r0 * LL + (mt + 1)) * VV + c;
                float* op1 = outp + ((size_t)(r0 + 8) * LL + (mt + 1)) * VV + c;
                *(float2*)op0 = make_float2(d[i][j][0] + p0.x, d[i][j][1] + p0.y);
                *(float2*)op1 = make_float2(d[i][j][2] + p1.x, d[i][j][3] + p1.y);
            }
        }
    }
}

// ---------------- small fp32 GEMM (context one-shots) ----------------
__global__ __launch_bounds__(256) void k_gemm(
    const float* __restrict__ A, int lda, const int* __restrict__ idx,
    const float* __restrict__ Bw, int ldb, int bofs,
    const float* __restrict__ bias,
    float* __restrict__ C, int N, int K, int accumulate)
{
    __shared__ float As[16][132];
    __shared__ float Bs[16][68];
    const int m0 = blockIdx.y * 128;
    const int n0 = blockIdx.x * 64;
    const int tid = threadIdx.x;
    const int rg = tid >> 4, cg = tid & 15;
    float acc[8][4];
#pragma unroll
    for (int i = 0; i < 8; i++)
#pragma unroll
        for (int j = 0; j < 4; j++) acc[i][j] = 0.f;
    const int r0 = tid >> 2, r1 = r0 + 64;
    const int kq0 = (tid & 3) * 4;
    const size_t aoff0 = (size_t)(idx ? idx[m0+r0] : m0+r0) * lda;
    const size_t aoff1 = (size_t)(idx ? idx[m0+r1] : m0+r1) * lda;
    const size_t boff  = (size_t)(n0 + r0) * ldb + bofs;
    for (int k0 = 0; k0 < K; k0 += 16) {
        float4 va0 = *reinterpret_cast<const float4*>(A + aoff0 + k0 + kq0);
        float4 va1 = *reinterpret_cast<const float4*>(A + aoff1 + k0 + kq0);
        float4 vb  = *reinterpret_cast<const float4*>(Bw + boff + k0 + kq0);
        As[kq0+0][r0] = va0.x; As[kq0+1][r0] = va0.y; As[kq0+2][r0] = va0.z; As[kq0+3][r0] = va0.w;
        As[kq0+0][r1] = va1.x; As[kq0+1][r1] = va1.y; As[kq0+2][r1] = va1.z; As[kq0+3][r1] = va1.w;
        Bs[kq0+0][r0] = vb.x;  Bs[kq0+1][r0] = vb.y;  Bs[kq0+2][r0] = vb.z;  Bs[kq0+3][r0] = vb.w;
        __syncthreads();
#pragma unroll
        for (int kk = 0; kk < 16; kk++) {
            float4 a0 = *reinterpret_cast<const float4*>(&As[kk][rg*8]);
            float4 a1 = *reinterpret_cast<const float4*>(&As[kk][rg*8+4]);
            float4 b  = *reinterpret_cast<const float4*>(&Bs[kk][cg*4]);
            float av[8] = {a0.x,a0.y,a0.z,a0.w,a1.x,a1.y,a1.z,a1.w};
            float bv[4] = {b.x,b.y,b.z,b.w};
#pragma unroll
            for (int i = 0; i < 8; i++)
#pragma unroll
                for (int j = 0; j < 4; j++) acc[i][j] += av[i]*bv[j];
        }
        __syncthreads();
    }
    float4 bb = make_float4(0.f,0.f,0.f,0.f);
    if (bias) bb = *reinterpret_cast<const float4*>(bias + n0 + cg*4);
#pragma unroll
    for (int i = 0; i < 8; i++) {
        float* cp = C + (size_t)(m0 + rg*8 + i) * N + n0 + cg*4;
        float4 v = make_float4(acc[i][0]+bb.x, acc[i][1]+bb.y, acc[i][2]+bb.z, acc[i][3]+bb.w);
        if (accumulate) {
            float4 p = *reinterpret_cast<const float4*>(cp);
            v.x += p.x; v.y += p.y; v.z += p.z; v.w += p.w;
        }
        *reinterpret_cast<float4*>(cp) = v;
    }
}

// ---------------- grid barrier ----------------
__device__ __forceinline__ void grid_bar(unsigned want) {
    __threadfence();
    __syncthreads();
    if (threadIdx.x == 0) {
        atomicAdd(&g_arrive, 1u);
        volatile unsigned* p = &g_arrive;
        while (*p < want) { }
    }
    __syncthreads();
}

// ---------------- tensor-core persistent GRU recurrence ----------------
// 128 blocks x 160 threads (4 mma warps + producer warp 4). Block owns h-cols j0..j0+7.
// N per block = 24: [r(8) | z(8) | n(8)]. K = 1024 tripled via dual W banks per A-hi chunk.
__global__ __launch_bounds__(160, 1)
void k_rec_tc(const unsigned char* __restrict__ Wimg,
              const float* __restrict__ gi, const float* __restrict__ gic,
              unsigned char* __restrict__ imgBase,
              const float* __restrict__ bhh,
              const float* __restrict__ ctx_init,   // null -> h0 = 0 (encoder)
              float* __restrict__ ctx_out,          // encoder: final h
              unsigned char* __restrict__ fcpack,   // decoder: fcin base
              int T)
{
    extern __shared__ unsigned char smem[];
    uint32_t sb = s2u(smem);
    int tid = threadIdx.x, wid = tid >> 5, lane = tid & 31;
    int bid = blockIdx.x;
    int j0 = bid * 8;

    if (tid == 0) {
        for (int s = 0; s < NST; s++) { MBAR_INIT(sb + 8 + s*8, 1); MBAR_INIT(sb + 40 + s*8, 4); }
        MBAR_INIT(sb + 72, 1);
    }
    __syncthreads();

    uint32_t ringb = sb + 1024;
    uint32_t wsm   = sb + 1024 + NST*RCH;

    if (wid == 4 && lane == 0) {
        MBAR_EXPECT_TX(sb + 72, RW_BYTES);
        bulk_g2s(wsm, Wimg + (size_t)bid * RW_BYTES, RW_BYTES, sb + 72);
    }

    // compute-warp per-thread state
    int w = wid, lr = lane >> 2, lc2 = (lane & 3) * 2;
    int chnk = j0 >> 6;                       // hi chunk index for this block's cols
    int cbyte = ((j0 + lc2) & 63) * 2;        // byte within chunk row (pair-aligned)
    float ho[2][2][2];
    float2 gx[2][2][3];
    float2 bh2[3];

    if (wid < 4) {
#pragma unroll
        for (int g = 0; g < 3; g++) bh2[g] = *(const float2*)(bhh + g*HH + j0 + lc2);
#pragma unroll
        for (int i = 0; i < 2; i++)
#pragma unroll
            for (int h = 0; h < 2; h++) {
                int b = w*32 + i*16 + h*8 + lr;
                if (ctx_init) {
                    float2 c = __ldcg((const float2*)(ctx_init + (size_t)b*HH + j0 + lc2));
                    ho[i][h][0] = c.x; ho[i][h][1] = c.y;
                } else { ho[i][h][0] = 0.f; ho[i][h][1] = 0.f; }
                if (gic) {
#pragma unroll
                    for (int g = 0; g < 3; g++)
                        gx[i][h][g] = *(const float2*)(gic + (size_t)b*H3 + g*HH + j0 + lc2);
                } else {
#pragma unroll
                    for (int g = 0; g < 3; g++) gx[i][h][g] = make_float2(0.f, 0.f);
                }
                if (!ctx_init) { // encoder: zero image[0] slots we own
                    unsigned sw = SW128((unsigned)(b*128 + cbyte));
                    __stcg((unsigned*)(imgBase + (size_t)chnk*RCH + sw), 0u);
                    __stcg((unsigned*)(imgBase + (size_t)(16+chnk)*RCH + sw), 0u);
                }
            }
    }
    grid_bar(1u * RGRID);
    if (wid < 4) MBAR_WAIT(sb + 72, 0);

    // ldmatrix address components
    int arow = lane & 15, ahalf = (lane >> 4) * 16, axm = (arow & 7) << 4;
    uint32_t aR[2];
    aR[0] = (uint32_t)(w*32 + arow) * 128;
    aR[1] = aR[0] + 16*128;
    int b4row = (lane >> 4)*8 + (lane & 7);
    int b4k   = ((lane >> 3) & 1) * 16;
    int b4xm  = (b4row & 7) << 4;
    int b2row = 16 + (lane & 7);
    int b2k   = ((lane >> 3) & 1) * 16;
    int b2xm  = (b2row & 7) << 4;

    for (int t = 0; t < T; t++) {
        const unsigned char* img_r = imgBase + (size_t)(t & 1) * IMGB;
        unsigned char*       img_w = imgBase + (size_t)((t + 1) & 1) * IMGB;

        if (wid == 4) {
            if (lane == 0) {
                for (int c = 0; c < RNCH; c++) {
                    unsigned idx = (unsigned)t * RNCH + c;
                    int s = idx & (NST - 1);
                    int eph = ((idx >> 2) & 1) ^ 1;
                    MBAR_WAIT_RLX(sb + 40 + s*8, eph);
                    MBAR_EXPECT_TX(sb + 8 + s*8, RCH);
                    bulk_g2s(ringb + s*RCH, img_r + (size_t)c*RCH, RCH, sb + 8 + s*8);
                }
            }
        } else {
            // prefetch gi for this step
            float2 gv[2][2][3];
#pragma unroll
            for (int i = 0; i < 2; i++)
#pragma unroll
                for (int h = 0; h < 2; h++) {
                    int b = w*32 + i*16 + h*8 + lr;
                    const float* gb = gi + ((size_t)t*BB + b)*H3 + j0 + lc2;
#pragma unroll
                    for (int g = 0; g < 3; g++)
                        gv[i][h][g] = __ldcg((const float2*)(gb + g*HH));
                }

            float d[2][3][4];
#pragma unroll
            for (int i = 0; i < 2; i++)
#pragma unroll
                for (int nf = 0; nf < 3; nf++)
#pragma unroll
                    for (int q = 0; q < 4; q++) d[i][nf][q] = 0.f;

            for (int c = 0; c < RNCH; c++) {
                unsigned idx = (unsigned)t * RNCH + c;
                int s = idx & (NST - 1);
                int fph = (idx >> 2) & 1;
                MBAR_WAIT(sb + 8 + s*8, fph);
                uint32_t Abase = ringb + s*RCH;
                int cw = (c < 16) ? c : (c - 16);
                uint32_t Wh = wsm + (uint32_t)cw * 3072;
#pragma unroll
                for (int ks = 0; ks < 4; ks++) {
                    int kb = ks * 32;
                    uint32_t afr[2][4];
#pragma unroll
                    for (int i = 0; i < 2; i++)
                        LDSM_X4(afr[i][0], afr[i][1], afr[i][2], afr[i][3],
                                Abase + aR[i] + (uint32_t)((kb + ahalf) ^ axm));
                    uint32_t b0,b1,b2,b3,b4,b5;
                    LDSM_X4(b0,b1,b2,b3, Wh + (uint32_t)(b4row*128) + (uint32_t)((kb + b4k) ^ b4xm));
                    LDSM_X2(b4,b5,       Wh + (uint32_t)(b2row*128) + (uint32_t)((kb + b2k) ^ b2xm));
#pragma unroll
                    for (int i = 0; i < 2; i++) {
                        MMA16816(d[i][0], afr[i][0], afr[i][1], afr[i][2], afr[i][3], b0, b1);
                        MMA16816(d[i][1], afr[i][0], afr[i][1], afr[i][2], afr[i][3], b2, b3);
                        MMA16816(d[i][2], afr[i][0], afr[i][1], afr[i][2], afr[i][3], b4, b5);
                    }
                    if (c < 16) { // A-hi chunk: also multiply Wl bank
                        uint32_t Wl = wsm + (uint32_t)(16 + c) * 3072;
                        LDSM_X4(b0,b1,b2,b3, Wl + (uint32_t)(b4row*128) + (uint32_t)((kb + b4k) ^ b4xm));
                        LDSM_X2(b4,b5,       Wl + (uint32_t)(b2row*128) + (uint32_t)((kb + b2k) ^ b2xm));
#pragma unroll
                        for (int i = 0; i < 2; i++) {
                            MMA16816(d[i][0], afr[i][0], afr[i][1], afr[i][2], afr[i][3], b0, b1);
                            MMA16816(d[i][1], afr[i][0], afr[i][1], afr[i][2], afr[i][3], b2, b3);
                            MMA16816(d[i][2], afr[i][0], afr[i][1], afr[i][2], afr[i][3], b4, b5);
                        }
                    }
                }
                __syncwarp();
                if (lane == 0) MBAR_ARRIVE(sb + 40 + s*8);
            }

            // GRU elementwise (fully in-register), pack hi/lo for next step
#pragma unroll
            for (int i = 0; i < 2; i++)
#pragma unroll
                for (int h = 0; h < 2; h++) {
                    int b = w*32 + i*16 + h*8 + lr;
#pragma unroll
                    for (int c2 = 0; c2 < 2; c2++) {
                        int q = h*2 + c2;
                        float gr = (c2 ? gv[i][h][0].y : gv[i][h][0].x) + (c2 ? gx[i][h][0].y : gx[i][h][0].x);
                        float gz = (c2 ? gv[i][h][1].y : gv[i][h][1].x) + (c2 ? gx[i][h][1].y : gx[i][h][1].x);
                        float gn = (c2 ? gv[i][h][2].y : gv[i][h][2].x) + (c2 ? gx[i][h][2].y : gx[i][h][2].x);
                        float hr = d[i][0][q] + (c2 ? bh2[0].y : bh2[0].x);
                        float hz = d[i][1][q] + (c2 ? bh2[1].y : bh2[1].x);
                        float hn = d[i][2][q] + (c2 ? bh2[2].y : bh2[2].x);
                        float rr = 1.f / (1.f + expf(-(gr + hr)));
                        float zz = 1.f / (1.f + expf(-(gz + hz)));
                        float nn = tanhf(gn + rr * hn);
                        ho[i][h][c2] = (1.f - zz) * nn + zz * ho[i][h][c2];
                    }
                    __nv_bfloat16 h0b = __float2bfloat16(ho[i][h][0]);
                    __nv_bfloat16 h1b = __float2bfloat16(ho[i][h][1]);
                    __nv_bfloat16 l0b = __float2bfloat16(ho[i][h][0] - __bfloat162float(h0b));
                    __nv_bfloat16 l1b = __float2bfloat16(ho[i][h][1] - __bfloat162float(h1b));
                    unsigned hiw = (unsigned)__bfloat16_as_ushort(h0b) | ((unsigned)__bfloat16_as_ushort(h1b) << 16);
                    unsigned low = (unsigned)__bfloat16_as_ushort(l0b) | ((unsigned)__bfloat16_as_ushort(l1b) << 16);
                    unsigned sw = SW128((unsigned)(b*128 + cbyte));
                    __stcg((unsigned*)(img_w + (size_t)chnk*RCH + sw), hiw);
                    __stcg((unsigned*)(img_w + (size_t)(16+chnk)*RCH + sw), low);
                    if (fcpack) {
                        size_t tb2 = (size_t)t * KC_FC * CHB;
                        __stcg((unsigned*)(fcpack + tb2 + (size_t)(24+chnk)*CHB + sw), hiw);
                        __stcg((unsigned*)(fcpack + tb2 + (size_t)(40+chnk)*CHB + sw), low);
                        __stcg((unsigned*)(fcpack + tb2 + (size_t)(56+chnk)*CHB + sw), hiw);
                    }
                    if (ctx_out && t == T-1)
                        __stcg((float2*)(ctx_out + (size_t)b*HH + j0 + lc2),
                               make_float2(ho[i][h][0], ho[i][h][1]));
                }
        }
        grid_bar((unsigned)(t + 2) * RGRID);
    }
}

// ---------------- small output pieces ----------------
__global__ void k_out_small(float* __restrict__ out) {
    int i = blockIdx.x * blockDim.x + threadIdx.x;
    const size_t NOUT = (size_t)BB * LL * VV;
    if (i < BB * VV) {
        int b = i / VV, v = i % VV;
        out[(size_t)b * LL * VV + v] = 0.f;
    }
    if (i < 3 * BB * HH) {
        out[NOUT + i] = (i < BB * HH) ? g_ctx[i] : 0.f;
    }
}

// ---------------- launch ----------------
extern "C" void kernel_launch(void* const* d_in, const int* in_sizes, int n_in,
                              void* d_out, int out_size) {
    const int*   seq     = (const int*)  d_in[0];
    const float* emb_enc = (const float*)d_in[2];
    const float* W_ih_e  = (const float*)d_in[3];
    const float* W_hh_e  = (const float*)d_in[4];
    const float* b_ih_e  = (const float*)d_in[5];
    const float* b_hh_e  = (const float*)d_in[6];
    const float* emb_dec = (const float*)d_in[7];
    const float* W_ih_d  = (const float*)d_in[8];
    const float* W_hh_d  = (const float*)d_in[9];
    const float* b_ih_d  = (const float*)d_in[10];
    const float* b_hh_d  = (const float*)d_in[11];
    const float* fc_W    = (const float*)d_in[12];
    const float* fc_b    = (const float*)d_in[13];

    void* p;
    cudaGetSymbolAddress(&p, g_idx_enc); int* idx_enc = (int*)p;
    cudaGetSymbolAddress(&p, g_idx_dec); int* idx_dec = (int*)p;
    cudaGetSymbolAddress(&p, g_gi_enc);  float* gi_enc = (float*)p;
    cudaGetSymbolAddress(&p, g_gi_dec);  float* gi_dec = (float*)p;
    cudaGetSymbolAddress(&p, g_gic);     float* gic = (float*)p;
    cudaGetSymbolAddress(&p, g_ctx);     float* ctx = (float*)p;
    cudaGetSymbolAddress(&p, g_Pc);      float* Pc = (float*)p;
    cudaGetSymbolAddress(&p, g_Xenc_p);  unsigned char* Xenc_p = (unsigned char*)p;
    cudaGetSymbolAddress(&p, g_fcin_p);  unsigned char* fcin_p = (unsigned char*)p;
    cudaGetSymbolAddress(&p, g_Wihe_p);  unsigned char* Wihe_p = (unsigned char*)p;
    cudaGetSymbolAddress(&p, g_Wihd_p);  unsigned char* Wihd_p = (unsigned char*)p;
    cudaGetSymbolAddress(&p, g_fcW_p);   unsigned char* fcW_p = (unsigned char*)p;
    cudaGetSymbolAddress(&p, g_WhhE_img); unsigned char* WhhE = (unsigned char*)p;
    cudaGetSymbolAddress(&p, g_WhhD_img); unsigned char* WhhD = (unsigned char*)p;
    cudaGetSymbolAddress(&p, g_hImg);     unsigned char* hImg = (unsigned char*)p;

    cudaFuncSetAttribute(k_mmagemm, cudaFuncAttributeMaxDynamicSharedMemorySize, SMEMSZ);
    cudaFuncSetAttribute(k_rec_tc,  cudaFuncAttributeMaxDynamicSharedMemorySize, RSM);

    // 1) indices + packing
    k_build_idx<<<(MENC + 255)/256, 256>>>(seq);
    k_pack_X<<<(MENC*64 + 255)/256, 256>>>(emb_enc, idx_enc, Xenc_p, MENC, KC_GI);
    k_pack_X<<<(MDEC*64 + 255)/256, 256>>>(emb_dec, idx_dec, fcin_p, MDEC, KC_FC);
    k_pack_W<<<(H3*64 + 255)/256, 256>>>(W_ih_e, EE,  0,  Wihe_p, H3, EE, 0,  KC_GI);
    k_pack_W<<<(H3*64 + 255)/256, 256>>>(W_ih_d, EH,  0,  Wihd_p, H3, EE, 0,  KC_GI);
    k_pack_W<<<(VV*64 + 255)/256, 256>>>(fc_W,   E2H, 0,  fcW_p,  VV, EE, 0,  KC_FC);
    k_pack_W<<<(VV*128 + 255)/256, 256>>>(fc_W,  E2H, EE, fcW_p,  VV, HH, 24, KC_FC);
    k_pack_Whh<<<(H3*128 + 255)/256, 256>>>(W_hh_e, WhhE);
    k_pack_Whh<<<(H3*128 + 255)/256, 256>>>(W_hh_d, WhhD);

    // 2) input-gate GEMMs (mma.sync, producer warp)
    k_mmagemm<<<dim3(NT_GI, MT_ENC), 288, SMEMSZ>>>(Xenc_p, KC_GI, Wihe_p, KC_GI, b_ih_e, gi_enc, H3, nullptr, nullptr, 0);
    k_mmagemm<<<dim3(NT_GI, MT_DEC), 288, SMEMSZ>>>(fcin_p, KC_FC, Wihd_p, KC_GI, b_ih_d, gi_dec, H3, nullptr, nullptr, 0);

    // 3) encoder recurrence (tensor-core persistent)
    k_reset_bar<<<1, 1>>>();
    k_rec_tc<<<RGRID, 160, RSM>>>(WhhE, gi_enc, nullptr, hImg, b_hh_e, nullptr, ctx, nullptr, LL);

    // 4) context one-shots
    k_gemm<<<dim3(H3/64, 1), 256>>>(ctx, HH, nullptr, W_ih_d, EH, EE, nullptr, gic, H3, HH, 0);
    k_gemm<<<dim3(VV/64, 1), 256>>>(ctx, HH, nullptr, fc_W, E2H, EE + HH, fc_b, Pc, VV, HH, 0);

    // 5) decoder recurrence (packs h2 into fcin chunks 24..71)
    k_reset_bar<<<1, 1>>>();
    k_rec_tc<<<RGRID, 160, RSM>>>(WhhD, gi_dec, gic, hImg, b_hh_d, ctx, nullptr, fcin_p, LDEC);

    // 6) fused fc GEMM -> writes d_out directly (adds Pc + fc_b)
    k_mmagemm<<<dim3(NT_FC, MT_DEC), 288, SMEMSZ>>>(fcin_p, KC_FC, fcW_p, KC_FC, nullptr, nullptr, 0, Pc, (float*)d_out, 1);

    // 7) small output pieces
    k_out_small<<<(3*BB*HH + 255)/256, 256>>>((float*)d_out);
}